// round 16
// baseline (speedup 1.0000x reference)
#include <cuda_runtime.h>
#include <cuda_fp16.h>
#include <cstdint>
#include <math.h>

// ---------------- problem constants ----------------
#define TT     4096
#define DMODEL 2048
#define NH     16
#define DQK    192     // 128 nope + 64 rope
#define DNOPE  128
#define DROPE  64
#define DV     128
#define RANK   512
#define KVF    (RANK + DROPE)          // 576
#define QSTRIDE (NH * DQK)             // 3072
#define KVBSTRIDE (NH * (DNOPE + DV))  // 4096
#define OSTRIDE (NH * DV)              // 2048
#define SCALE 0.07216878364870323f     // 192^-0.5

// ---------------- scratch (no cudaMalloc allowed) ----------------
__device__ float g_kvfull[TT * KVF];
__device__ float g_cos[TT * 32];
__device__ float g_sin[TT * 32];
__device__ __half g_qh[TT * QSTRIDE];
__device__ __half g_kvbh[TT * KVBSTRIDE];
__device__ __half g_vth[NH * 128 * TT];    // V^T: [h*128+dv][t]
__device__ __half g_kpeh[TT * DROPE];
__device__ __half g_xh[TT * DMODEL];
__device__ __half g_wqh[3072 * DMODEL];
__device__ __half g_wkvah[KVF * DMODEL];
__device__ __half g_wkvbh[KVBSTRIDE * RANK];
__device__ __half g_woh[DMODEL * DMODEL];
__device__ __half g_kvnh[TT * RANK];
__device__ __half g_ah[TT * OSTRIDE];

// ---------------- helpers ----------------
__device__ __forceinline__ void mma_fp16(float c[4],
    unsigned a0, unsigned a1, unsigned a2, unsigned a3,
    unsigned b0, unsigned b1)
{
    asm volatile(
        "mma.sync.aligned.m16n8k16.row.col.f32.f16.f16.f32 "
        "{%0,%1,%2,%3},{%4,%5,%6,%7},{%8,%9},{%0,%1,%2,%3};"
        : "+f"(c[0]), "+f"(c[1]), "+f"(c[2]), "+f"(c[3])
        : "r"(a0), "r"(a1), "r"(a2), "r"(a3), "r"(b0), "r"(b1));
}
__device__ __forceinline__ void cp16(void* sptr, const void* gptr) {
    unsigned a = (unsigned)__cvta_generic_to_shared(sptr);
    asm volatile("cp.async.cg.shared.global [%0], [%1], 16;" :: "r"(a), "l"(gptr));
}
#define CP_COMMIT() asm volatile("cp.async.commit_group;")
__device__ __forceinline__ unsigned pack2(float x, float y) {
    __half2 h = __floats2half2_rn(x, y);
    return *reinterpret_cast<unsigned*>(&h);
}
// ldmatrix x4: loads 4 m8n8 b16 tiles; lane L supplies the address of row
// (L&15) at k-half offset ((L>>4)*8) -> regs land in mma fragment order.
#define LDSM4(r0, r1, r2, r3, addr) \
    asm volatile("ldmatrix.sync.aligned.m8n8.x4.shared.b16 {%0,%1,%2,%3}, [%4];" \
        : "=r"(r0), "=r"(r1), "=r"(r2), "=r"(r3) : "r"(addr))

// ---------------- elementwise preprocessing ----------------
__global__ void tohalf_kernel(const float* __restrict__ src,
                              __half* __restrict__ dst, int n4)
{
    int i = blockIdx.x * blockDim.x + threadIdx.x;
    if (i < n4) {
        float4 v = ((const float4*)src)[i];
        ((__half2*)dst)[2 * i]     = __floats2half2_rn(v.x, v.y);
        ((__half2*)dst)[2 * i + 1] = __floats2half2_rn(v.z, v.w);
    }
}

__global__ void rope_table_kernel()
{
    int idx = blockIdx.x * blockDim.x + threadIdx.x;   // < TT*32
    int i = idx & 31, t = idx >> 5;
    double inv = pow(10000.0, -(double)(2 * i) / 64.0);
    double sd, cd;
    sincos((double)t * inv, &sd, &cd);
    g_cos[idx] = (float)cd;
    g_sin[idx] = (float)sd;
}

// =================================================================
// fp16 MMA GEMM: CTA tile 128 x (NFRAG*16), KC=64, 3-stage cp.async,
// 2 CTAs/SM, stride 72 halves. Fragments via ldmatrix.x4.
// MODE 0: fp32 raw out. MODE 1: rope(q_pe) + fp16 out.
// MODE 2: fp16 out (full) + transposed fp16 V^T out.
// =================================================================
#define SH   72

template<int NFRAG, int MODE>
__global__ void __launch_bounds__(256, 2) gemm_h(
    const __half* __restrict__ A, const __half* __restrict__ B,
    float* __restrict__ Cf, __half* __restrict__ Ch,
    __half* __restrict__ Cvt, int N, int K)
{
    constexpr int BN   = NFRAG * 16;
    constexpr int ASZH = 128 * SH;
    constexpr int BSZH = BN * SH;
    extern __shared__ __half smh[];
    __half* As = smh;
    __half* Bs = smh + 3 * ASZH;

    const int tid = threadIdx.x;
    const int lane = tid & 31, w = tid >> 5;
    const int g = lane >> 2, tig = lane & 3;
    const int bm = blockIdx.y * 128, bn = blockIdx.x * BN;
    const int m0 = (w >> 1) * 32;
    const int n0 = (w & 1) * (BN / 2);
    const int lrow = lane & 15, lkh = (lane >> 4) * 8;

    const int arow = tid >> 1, acs = (tid & 1) * 32;
    constexpr int TPR = 256 / BN;
    constexpr int BW  = 64 / TPR;
    constexpr int NB16 = BW / 8;
    const int brow = tid / TPR, bcs = (tid % TPR) * BW;

    const __half* Ap = A + (size_t)(bm + arow) * K + acs;
    const __half* Bp = B + (size_t)(bn + brow) * K + bcs;

    const int nsteps = K >> 6;

    auto issue = [&](int st, int k0) {
        __half* Ad = As + st * ASZH + arow * SH + acs;
#pragma unroll
        for (int u = 0; u < 4; u++) cp16(Ad + u * 8, Ap + k0 + u * 8);
        __half* Bd = Bs + st * BSZH + brow * SH + bcs;
#pragma unroll
        for (int u = 0; u < NB16; u++) cp16(Bd + u * 8, Bp + k0 + u * 8);
        CP_COMMIT();
    };

    issue(0, 0);
    issue(1, 64);

    // per-thread ldmatrix byte offsets (relative to stage base)
    const unsigned sA = (unsigned)__cvta_generic_to_shared(As);
    const unsigned sB = (unsigned)__cvta_generic_to_shared(Bs);
    unsigned aoff[2], boff[NFRAG / 2];
#pragma unroll
    for (int i = 0; i < 2; i++)
        aoff[i] = ((m0 + i * 16 + lrow) * SH + lkh) * 2;
#pragma unroll
    for (int nf = 0; nf < NFRAG / 2; nf++)
        boff[nf] = ((n0 + nf * 16 + lrow) * SH + lkh) * 2;

    float c[2][NFRAG][4] = {};

    int st = 0;
    for (int i = 0; i < nsteps; i++) {
        if (i < nsteps - 1) asm volatile("cp.async.wait_group 1;");
        else                asm volatile("cp.async.wait_group 0;");
        __syncthreads();

        const unsigned abase = sA + st * (ASZH * 2);
        const unsigned bbase = sB + st * (BSZH * 2);
#pragma unroll
        for (int ks = 0; ks < 4; ks++) {
            unsigned a[2][4];
#pragma unroll
            for (int ii = 0; ii < 2; ii++)
                LDSM4(a[ii][0], a[ii][1], a[ii][2], a[ii][3],
                      abase + aoff[ii] + ks * 32);
            unsigned b[NFRAG][2];
#pragma unroll
            for (int nf = 0; nf < NFRAG / 2; nf++) {
                unsigned t0, t1, t2, t3;
                LDSM4(t0, t1, t2, t3, bbase + boff[nf] + ks * 32);
                b[2 * nf][0] = t0;     b[2 * nf][1] = t2;
                b[2 * nf + 1][0] = t1; b[2 * nf + 1][1] = t3;
            }
#pragma unroll
            for (int j = 0; j < NFRAG; j++)
#pragma unroll
                for (int ii = 0; ii < 2; ii++)
                    mma_fp16(c[ii][j], a[ii][0], a[ii][1], a[ii][2], a[ii][3],
                             b[j][0], b[j][1]);
        }
        if (i + 2 < nsteps) issue((st + 2) % 3, (i + 2) * 64);
        st = (st + 1) % 3;
    }

    // ---- epilogue ----
#pragma unroll
    for (int i = 0; i < 2; i++) {
        int r0 = bm + m0 + i * 16 + g;
#pragma unroll
        for (int j = 0; j < NFRAG; j++) {
            int cc = bn + n0 + j * 8 + tig * 2;
            float v00 = c[i][j][0], v01 = c[i][j][1];
            float v10 = c[i][j][2], v11 = c[i][j][3];
            if (MODE == 1) {
                int hc = cc % DQK;
                if (hc >= DNOPE) {
                    int pi = (hc - DNOPE) >> 1;
                    float c0 = g_cos[r0 * 32 + pi], s0 = g_sin[r0 * 32 + pi];
                    float t0 = v00 * c0 - v01 * s0;
                    v01 = v00 * s0 + v01 * c0; v00 = t0;
                    float c1 = g_cos[(r0 + 8) * 32 + pi], s1 = g_sin[(r0 + 8) * 32 + pi];
                    float t1 = v10 * c1 - v11 * s1;
                    v11 = v10 * s1 + v11 * c1; v10 = t1;
                }
                *(__half2*)&Ch[(size_t)r0 * N + cc] = __floats2half2_rn(v00, v01);
                *(__half2*)&Ch[(size_t)(r0 + 8) * N + cc] = __floats2half2_rn(v10, v11);
            } else if (MODE == 2) {
                *(__half2*)&Ch[(size_t)r0 * N + cc] = __floats2half2_rn(v00, v01);
                *(__half2*)&Ch[(size_t)(r0 + 8) * N + cc] = __floats2half2_rn(v10, v11);
                int hc = cc & 255;
                if (hc >= 128) {
                    int dvg = (cc >> 8) * 128 + (hc - 128);
                    Cvt[(size_t)dvg * TT + r0]           = __float2half_rn(v00);
                    Cvt[(size_t)(dvg + 1) * TT + r0]     = __float2half_rn(v01);
                    Cvt[(size_t)dvg * TT + r0 + 8]       = __float2half_rn(v10);
                    Cvt[(size_t)(dvg + 1) * TT + r0 + 8] = __float2half_rn(v11);
                }
            } else {
                *(float2*)&Cf[(size_t)r0 * N + cc] = make_float2(v00, v01);
                *(float2*)&Cf[(size_t)(r0 + 8) * N + cc] = make_float2(v10, v11);
            }
        }
    }
}

// =================================================================
// LayerNorm(kv) -> fp16 kvn; RoPE(k_pe) -> fp16 kpe
// =================================================================
__global__ void ln_ropek_kernel(
    const float* __restrict__ kvf, const float* __restrict__ gamma,
    const float* __restrict__ beta,
    __half* __restrict__ kvnh, __half* __restrict__ kpeh)
{
    int row = blockIdx.x, tid = threadIdx.x;
    __shared__ float red[16];
    float a = kvf[row * KVF + tid];
    float b = kvf[row * KVF + 256 + tid];
    float s1 = a + b, s2 = a * a + b * b;
#pragma unroll
    for (int off = 16; off; off >>= 1) {
        s1 += __shfl_xor_sync(0xffffffffu, s1, off);
        s2 += __shfl_xor_sync(0xffffffffu, s2, off);
    }
    if ((tid & 31) == 0) { red[tid >> 5] = s1; red[8 + (tid >> 5)] = s2; }
    __syncthreads();
    float t1 = 0.f, t2 = 0.f;
#pragma unroll
    for (int i = 0; i < 8; i++) { t1 += red[i]; t2 += red[8 + i]; }
    float mean = t1 * (1.f / 512.f);
    float var  = t2 * (1.f / 512.f) - mean * mean;
    float rstd = rsqrtf(var + 1e-5f);
    kvnh[row * RANK + tid] =
        __float2half_rn((a - mean) * rstd * gamma[tid] + beta[tid]);
    kvnh[row * RANK + 256 + tid] =
        __float2half_rn((b - mean) * rstd * gamma[256 + tid] + beta[256 + tid]);
    if (tid < 32) {
        int i = tid;
        float c = g_cos[row * 32 + i], s = g_sin[row * 32 + i];
        float x1 = kvf[row * KVF + RANK + 2 * i];
        float x2 = kvf[row * KVF + RANK + 2 * i + 1];
        kpeh[row * DROPE + 2 * i]     = __float2half_rn(x1 * c - x2 * s);
        kpeh[row * DROPE + 2 * i + 1] = __float2half_rn(x1 * s + x2 * c);
    }
}

// =================================================================
// Flash attention v7: register softmax + double-buffered K/V^T
// (from R15) with all fragment loads via ldmatrix.x4.
// =================================================================
#define SQH  200    // Q/K smem stride in halves
#define SVTH 72     // V^T stride in halves
#define QR   128
#define KSZH (64 * SQH)
#define VSZH (128 * SVTH)
#define ATTN_SMEM_BYTES ((QR*SQH + 2*KSZH + 2*VSZH) * 2)

__global__ void __launch_bounds__(256, 1) attn_kernel(
    const __half* __restrict__ qh, const __half* __restrict__ kvbh,
    const __half* __restrict__ kpeh, const __half* __restrict__ vth,
    __half* __restrict__ ah)
{
    extern __shared__ char smb[];
    __half* Qh = (__half*)smb;                  // [128][200]
    __half* Kh = Qh + QR * SQH;                 // [2][64][200]
    __half* Vh = Kh + 2 * KSZH;                 // [2][128][72]

    const int tid = threadIdx.x;
    const int lane = tid & 31, w = tid >> 5;
    const int g = lane >> 2, tig = lane & 3;
    const int m0 = w * 16;                       // warp q-row base
    const int h  = blockIdx.y;
    const int iq = (int)(gridDim.x - 1) - (int)blockIdx.x;  // big tiles first
    const int q0 = iq * QR;
    const int lr = tid >> 2;                     // 0..63  (K loads)
    const int seg = tid & 3;                     // 0..3
    const int qr = tid >> 1;                     // 0..127 (Q/V loads)
    const int qs = tid & 1;                      // 0..1
    const int lrow = lane & 15, lkh = (lane >> 4) * 8;

    auto issue_kv = [&](int jt, int buf) {
        int t = jt * 64 + lr;
        const __half* kn = kvbh + (size_t)t * KVBSTRIDE + h * 256;
        const __half* kp = kpeh + (size_t)t * DROPE;
        __half* Kb = Kh + buf * KSZH;
#pragma unroll
        for (int u = 0; u < 6; u++) {
            int k = seg * 48 + u * 8;
            const __half* src = (k < 128) ? (kn + k) : (kp + (k - 128));
            cp16(&Kb[lr * SQH + k], src);
        }
        const __half* vsrc = vth + ((size_t)(h * 128 + qr)) * TT + jt * 64 + qs * 32;
        __half* Vb = Vh + buf * VSZH;
#pragma unroll
        for (int u = 0; u < 4; u++)
            cp16(&Vb[qr * SVTH + qs * 32 + u * 8], vsrc + u * 8);
        CP_COMMIT();
    };

    issue_kv(0, 0);
    {
        const __half* src = qh + (size_t)(q0 + qr) * QSTRIDE + h * DQK + qs * 96;
#pragma unroll
        for (int u = 0; u < 12; u++)
            *(uint4*)&Qh[qr * SQH + qs * 96 + u * 8] = *(const uint4*)(src + u * 8);
    }

    // ldmatrix byte offsets
    const unsigned sQ = (unsigned)__cvta_generic_to_shared(Qh);
    const unsigned sK = (unsigned)__cvta_generic_to_shared(Kh);
    const unsigned sV = (unsigned)__cvta_generic_to_shared(Vh);
    const unsigned qoff = ((m0 + lrow) * SQH + lkh) * 2;
    unsigned koff[4], voff[8];
#pragma unroll
    for (int nf = 0; nf < 4; nf++) koff[nf] = ((nf * 16 + lrow) * SQH + lkh) * 2;
#pragma unroll
    for (int nf = 0; nf < 8; nf++) voff[nf] = ((nf * 16 + lrow) * SVTH + lkh) * 2;

    float mr0 = -INFINITY, mr1 = -INFINITY;
    float lr0 = 0.f, lr1 = 0.f;
    float o[16][4] = {};

    const int jmax = 2 * iq + 1;
    for (int jt = 0; jt <= jmax; jt++) {
        __syncthreads();
        if (jt < jmax) {
            issue_kv(jt + 1, (jt + 1) & 1);
            asm volatile("cp.async.wait_group 1;");
        } else {
            asm volatile("cp.async.wait_group 0;");
        }
        __syncthreads();

        const unsigned kbase = sK + (jt & 1) * (KSZH * 2);
        const unsigned vbase = sV + (jt & 1) * (VSZH * 2);

        // ---- S = Q K^T, fp16 (12 k16-steps), ldmatrix frags ----
        float s[8][4] = {};
#pragma unroll
        for (int ks = 0; ks < 12; ks++) {
            unsigned a0, a1, a2, a3;
            LDSM4(a0, a1, a2, a3, sQ + qoff + ks * 32);
            unsigned b[8][2];
#pragma unroll
            for (int nf = 0; nf < 4; nf++) {
                unsigned t0, t1, t2, t3;
                LDSM4(t0, t1, t2, t3, kbase + koff[nf] + ks * 32);
                b[2 * nf][0] = t0;     b[2 * nf][1] = t2;
                b[2 * nf + 1][0] = t1; b[2 * nf + 1][1] = t3;
            }
#pragma unroll
            for (int j = 0; j < 8; j++)
                mma_fp16(s[j], a0, a1, a2, a3, b[j][0], b[j][1]);
        }

        // ---- mask + scale in registers ----
        {
            int gr0 = q0 + m0 + g, gr1 = gr0 + 8;
#pragma unroll
            for (int j = 0; j < 8; j++) {
                int gc0 = jt * 64 + j * 8 + tig * 2, gc1 = gc0 + 1;
                s[j][0] = (gr0 >= gc0) ? s[j][0] * SCALE : -INFINITY;
                s[j][1] = (gr0 >= gc1) ? s[j][1] * SCALE : -INFINITY;
                s[j][2] = (gr1 >= gc0) ? s[j][2] * SCALE : -INFINITY;
                s[j][3] = (gr1 >= gc1) ? s[j][3] * SCALE : -INFINITY;
            }
        }

        // ---- register softmax: quad shfl reductions ----
        float mx0 = -INFINITY, mx1 = -INFINITY;
#pragma unroll
        for (int j = 0; j < 8; j++) {
            mx0 = fmaxf(mx0, fmaxf(s[j][0], s[j][1]));
            mx1 = fmaxf(mx1, fmaxf(s[j][2], s[j][3]));
        }
        mx0 = fmaxf(mx0, __shfl_xor_sync(0xffffffffu, mx0, 1));
        mx0 = fmaxf(mx0, __shfl_xor_sync(0xffffffffu, mx0, 2));
        mx1 = fmaxf(mx1, __shfl_xor_sync(0xffffffffu, mx1, 1));
        mx1 = fmaxf(mx1, __shfl_xor_sync(0xffffffffu, mx1, 2));
        float mn0 = fmaxf(mr0, mx0), mn1 = fmaxf(mr1, mx1);
        float al0 = __expf(mr0 - mn0), al1 = __expf(mr1 - mn1);
        float sum0 = 0.f, sum1 = 0.f;
#pragma unroll
        for (int j = 0; j < 8; j++) {
            s[j][0] = __expf(s[j][0] - mn0);
            s[j][1] = __expf(s[j][1] - mn0);
            s[j][2] = __expf(s[j][2] - mn1);
            s[j][3] = __expf(s[j][3] - mn1);
            sum0 += s[j][0] + s[j][1];
            sum1 += s[j][2] + s[j][3];
        }
        sum0 += __shfl_xor_sync(0xffffffffu, sum0, 1);
        sum0 += __shfl_xor_sync(0xffffffffu, sum0, 2);
        sum1 += __shfl_xor_sync(0xffffffffu, sum1, 1);
        sum1 += __shfl_xor_sync(0xffffffffu, sum1, 2);
        lr0 = lr0 * al0 + sum0;  mr0 = mn0;
        lr1 = lr1 * al1 + sum1;  mr1 = mn1;

        // ---- rescale O, then O += P @ V (P from S frags; V via ldmatrix) ----
#pragma unroll
        for (int nt = 0; nt < 16; nt++) {
            o[nt][0] *= al0; o[nt][1] *= al0;
            o[nt][2] *= al1; o[nt][3] *= al1;
        }
#pragma unroll
        for (int ks = 0; ks < 4; ks++) {
            unsigned a0 = pack2(s[2 * ks][0],     s[2 * ks][1]);
            unsigned a1 = pack2(s[2 * ks][2],     s[2 * ks][3]);
            unsigned a2 = pack2(s[2 * ks + 1][0], s[2 * ks + 1][1]);
            unsigned a3 = pack2(s[2 * ks + 1][2], s[2 * ks + 1][3]);
            unsigned b[16][2];
#pragma unroll
            for (int nf = 0; nf < 8; nf++) {
                unsigned t0, t1, t2, t3;
                LDSM4(t0, t1, t2, t3, vbase + voff[nf] + ks * 32);
                b[2 * nf][0] = t0;     b[2 * nf][1] = t2;
                b[2 * nf + 1][0] = t1; b[2 * nf + 1][1] = t3;
            }
#pragma unroll
            for (int nt = 0; nt < 16; nt++)
                mma_fp16(o[nt], a0, a1, a2, a3, b[nt][0], b[nt][1]);
        }
    }

    {
        float inv0 = 1.f / lr0;
        float inv1 = 1.f / lr1;
        size_t r0 = (size_t)(q0 + m0 + g) * OSTRIDE + h * DV;
        size_t r1 = (size_t)(q0 + m0 + 8 + g) * OSTRIDE + h * DV;
#pragma unroll
        for (int nt = 0; nt < 16; nt++) {
            int cc = nt * 8 + tig * 2;
            *(__half2*)(ah + r0 + cc) = __floats2half2_rn(o[nt][0] * inv0, o[nt][1] * inv0);
            *(__half2*)(ah + r1 + cc) = __floats2half2_rn(o[nt][2] * inv1, o[nt][3] * inv1);
        }
    }
}

// =================================================================
// launch
// =================================================================
#define GSMH8 (3 * (128 * SH + 128 * SH) * 2)   // 110592 B
#define GSMH4 (3 * (128 * SH + 64 * SH) * 2)    // 82944 B

extern "C" void kernel_launch(void* const* d_in, const int* in_sizes, int n_in,
                              void* d_out, int out_size)
{
    const float* x     = (const float*)d_in[0];
    const float* wq    = (const float*)d_in[1];
    const float* wkv_a = (const float*)d_in[2];
    const float* gamma = (const float*)d_in[3];
    const float* beta  = (const float*)d_in[4];
    const float* wkv_b = (const float*)d_in[5];
    const float* wo    = (const float*)d_in[6];
    float* out = (float*)d_out;

    float *gkvf;
    __half *qh, *kvbh, *vth, *kpeh, *xh, *wqh, *wkvah, *wkvbh, *woh, *kvnh, *ah;
    cudaGetSymbolAddress((void**)&gkvf,  g_kvfull);
    cudaGetSymbolAddress((void**)&qh,    g_qh);
    cudaGetSymbolAddress((void**)&kvbh,  g_kvbh);
    cudaGetSymbolAddress((void**)&vth,   g_vth);
    cudaGetSymbolAddress((void**)&kpeh,  g_kpeh);
    cudaGetSymbolAddress((void**)&xh,    g_xh);
    cudaGetSymbolAddress((void**)&wqh,   g_wqh);
    cudaGetSymbolAddress((void**)&wkvah, g_wkvah);
    cudaGetSymbolAddress((void**)&wkvbh, g_wkvbh);
    cudaGetSymbolAddress((void**)&woh,   g_woh);
    cudaGetSymbolAddress((void**)&kvnh,  g_kvnh);
    cudaGetSymbolAddress((void**)&ah,    g_ah);

    cudaFuncSetAttribute(gemm_h<8, 1>, cudaFuncAttributeMaxDynamicSharedMemorySize, GSMH8);
    cudaFuncSetAttribute(gemm_h<8, 2>, cudaFuncAttributeMaxDynamicSharedMemorySize, GSMH8);
    cudaFuncSetAttribute(gemm_h<8, 0>, cudaFuncAttributeMaxDynamicSharedMemorySize, GSMH8);
    cudaFuncSetAttribute(gemm_h<4, 0>, cudaFuncAttributeMaxDynamicSharedMemorySize, GSMH4);
    cudaFuncSetAttribute(attn_kernel, cudaFuncAttributeMaxDynamicSharedMemorySize, ATTN_SMEM_BYTES);

    // tables + fp16 operand copies
    rope_table_kernel<<<(TT * 32) / 256, 256>>>();
    tohalf_kernel<<<(TT * DMODEL / 4 + 255) / 256, 256>>>(x, xh, TT * DMODEL / 4);
    tohalf_kernel<<<(3072 * DMODEL / 4 + 255) / 256, 256>>>(wq, wqh, 3072 * DMODEL / 4);
    tohalf_kernel<<<(KVF * DMODEL / 4 + 255) / 256, 256>>>(wkv_a, wkvah, KVF * DMODEL / 4);
    tohalf_kernel<<<(KVBSTRIDE * RANK / 4 + 255) / 256, 256>>>(wkv_b, wkvbh, KVBSTRIDE * RANK / 4);
    tohalf_kernel<<<(DMODEL * DMODEL / 4 + 255) / 256, 256>>>(wo, woh, DMODEL * DMODEL / 4);

    // q = x @ wq^T (+fused rope) -> fp16       4096 x 3072, K=2048
    gemm_h<8, 1><<<dim3(3072 / 128, TT / 128), 256, GSMH8>>>(
        xh, wqh, nullptr, qh, nullptr, 3072, DMODEL);
    // kv_full = x @ wkv_a^T -> fp32            4096 x 576, K=2048
    gemm_h<4, 0><<<dim3(KVF / 64, TT / 128), 256, GSMH4>>>(
        xh, wkvah, gkvf, nullptr, nullptr, KVF, DMODEL);
    // layernorm(kv) -> fp16 kvn; rope(k_pe) -> fp16
    ln_ropek_kernel<<<TT, 256>>>(gkvf, gamma, beta, kvnh, kpeh);
    // kvb = kvn @ wkv_b^T -> fp16 + V^T fp16   4096 x 4096, K=512
    gemm_h<8, 2><<<dim3(KVBSTRIDE / 128, TT / 128), 256, GSMH8>>>(
        kvnh, wkvbh, nullptr, kvbh, vth, KVBSTRIDE, RANK);
    // attention -> fp16
    attn_kernel<<<dim3(TT / QR, NH), 256, ATTN_SMEM_BYTES>>>(qh, kvbh, kpeh, vth, ah);
    // out = attn @ wo^T -> fp32                4096 x 2048, K=2048
    gemm_h<8, 0><<<dim3(DMODEL / 128, TT / 128), 256, GSMH8>>>(
        ah, woh, out, nullptr, nullptr, DMODEL, DMODEL);
}

// round 17
// speedup vs baseline: 1.0122x; 1.0122x over previous
#include <cuda_runtime.h>
#include <cuda_fp16.h>
#include <cstdint>
#include <math.h>

// ---------------- problem constants ----------------
#define TT     4096
#define DMODEL 2048
#define NH     16
#define DQK    192     // 128 nope + 64 rope
#define DNOPE  128
#define DROPE  64
#define DV     128
#define RANK   512
#define KVF    (RANK + DROPE)          // 576
#define QSTRIDE (NH * DQK)             // 3072
#define KVBSTRIDE (NH * (DNOPE + DV))  // 4096
#define OSTRIDE (NH * DV)              // 2048
#define SCALE 0.07216878364870323f     // 192^-0.5

// ---------------- scratch (no cudaMalloc allowed) ----------------
__device__ float g_kvfull[TT * KVF];
__device__ float g_cos[TT * 32];
__device__ float g_sin[TT * 32];
__device__ __half g_qh[TT * QSTRIDE];
__device__ __half g_kvbh[TT * KVBSTRIDE];
__device__ __half g_kpeh[TT * DROPE];
__device__ __half g_xh[TT * DMODEL];
__device__ __half g_wqh[3072 * DMODEL];
__device__ __half g_wkvah[KVF * DMODEL];
__device__ __half g_wkvbh[KVBSTRIDE * RANK];
__device__ __half g_woh[DMODEL * DMODEL];
__device__ __half g_kvnh[TT * RANK];
__device__ __half g_ah[TT * OSTRIDE];

// ---------------- helpers ----------------
__device__ __forceinline__ void mma_fp16(float c[4],
    unsigned a0, unsigned a1, unsigned a2, unsigned a3,
    unsigned b0, unsigned b1)
{
    asm volatile(
        "mma.sync.aligned.m16n8k16.row.col.f32.f16.f16.f32 "
        "{%0,%1,%2,%3},{%4,%5,%6,%7},{%8,%9},{%0,%1,%2,%3};"
        : "+f"(c[0]), "+f"(c[1]), "+f"(c[2]), "+f"(c[3])
        : "r"(a0), "r"(a1), "r"(a2), "r"(a3), "r"(b0), "r"(b1));
}
__device__ __forceinline__ void cp16(void* sptr, const void* gptr) {
    unsigned a = (unsigned)__cvta_generic_to_shared(sptr);
    asm volatile("cp.async.cg.shared.global [%0], [%1], 16;" :: "r"(a), "l"(gptr));
}
#define CP_COMMIT() asm volatile("cp.async.commit_group;")
__device__ __forceinline__ unsigned pack2(float x, float y) {
    __half2 h = __floats2half2_rn(x, y);
    return *reinterpret_cast<unsigned*>(&h);
}
// transposed ldmatrix: loads 4 8x8 b16 tiles transposed (for V in PV)
#define LDSM4T(r0, r1, r2, r3, addr) \
    asm volatile("ldmatrix.sync.aligned.m8n8.x4.trans.shared.b16 {%0,%1,%2,%3}, [%4];" \
        : "=r"(r0), "=r"(r1), "=r"(r2), "=r"(r3) : "r"(addr))

// ---------------- elementwise preprocessing ----------------
// merged fp32->fp16 conversion of x + 4 weights (one launch)
#define N4_X   (TT * DMODEL / 4)
#define N4_WQ  (3072 * DMODEL / 4)
#define N4_WA  (KVF * DMODEL / 4)
#define N4_WB  (KVBSTRIDE * RANK / 4)
#define N4_WO  (DMODEL * DMODEL / 4)
#define N4_TOT (N4_X + N4_WQ + N4_WA + N4_WB + N4_WO)

__global__ void tohalf_all_kernel(
    const float* __restrict__ x,  const float* __restrict__ wq,
    const float* __restrict__ wa, const float* __restrict__ wb,
    const float* __restrict__ wo)
{
    int i = blockIdx.x * blockDim.x + threadIdx.x;
    const float* src; __half* dst; int off;
    if (i >= N4_TOT) return;
    if (i < N4_X)                        { src = x;  dst = g_xh;    off = i; }
    else if (i < N4_X + N4_WQ)           { src = wq; dst = g_wqh;   off = i - N4_X; }
    else if (i < N4_X + N4_WQ + N4_WA)   { src = wa; dst = g_wkvah; off = i - N4_X - N4_WQ; }
    else if (i < N4_X + N4_WQ + N4_WA + N4_WB)
                                         { src = wb; dst = g_wkvbh; off = i - N4_X - N4_WQ - N4_WA; }
    else                                 { src = wo; dst = g_woh;   off = i - N4_X - N4_WQ - N4_WA - N4_WB; }
    float4 v = ((const float4*)src)[off];
    ((__half2*)dst)[2 * off]     = __floats2half2_rn(v.x, v.y);
    ((__half2*)dst)[2 * off + 1] = __floats2half2_rn(v.z, v.w);
}

__global__ void rope_table_kernel()
{
    int idx = blockIdx.x * blockDim.x + threadIdx.x;   // < TT*32
    int i = idx & 31, t = idx >> 5;
    double inv = pow(10000.0, -(double)(2 * i) / 64.0);
    double sd, cd;
    sincos((double)t * inv, &sd, &cd);
    g_cos[idx] = (float)cd;
    g_sin[idx] = (float)sd;
}

// =================================================================
// fp16 MMA GEMM (R15 hot loops): CTA tile 128 x (NFRAG*16), KC=64,
// 3-stage cp.async, 2 CTAs/SM, stride 72 halves.
// MODE 0: fp32 raw out. MODE 1: rope(q_pe) + fp16 out. MODE 2: fp16 out.
// =================================================================
#define SH   72
#define SH32 36

template<int NFRAG, int MODE>
__global__ void __launch_bounds__(256, 2) gemm_h(
    const __half* __restrict__ A, const __half* __restrict__ B,
    float* __restrict__ Cf, __half* __restrict__ Ch, int N, int K)
{
    constexpr int BN   = NFRAG * 16;
    constexpr int ASZH = 128 * SH;
    constexpr int BSZH = BN * SH;
    extern __shared__ __half smh[];
    __half* As = smh;
    __half* Bs = smh + 3 * ASZH;

    const int tid = threadIdx.x;
    const int lane = tid & 31, w = tid >> 5;
    const int g = lane >> 2, tig = lane & 3;
    const int bm = blockIdx.y * 128, bn = blockIdx.x * BN;
    const int m0 = (w >> 1) * 32;
    const int n0 = (w & 1) * (BN / 2);

    const int arow = tid >> 1, acs = (tid & 1) * 32;
    constexpr int TPR = 256 / BN;
    constexpr int BW  = 64 / TPR;
    constexpr int NB16 = BW / 8;
    const int brow = tid / TPR, bcs = (tid % TPR) * BW;

    const __half* Ap = A + (size_t)(bm + arow) * K + acs;
    const __half* Bp = B + (size_t)(bn + brow) * K + bcs;

    const int nsteps = K >> 6;

    auto issue = [&](int st, int k0) {
        __half* Ad = As + st * ASZH + arow * SH + acs;
#pragma unroll
        for (int u = 0; u < 4; u++) cp16(Ad + u * 8, Ap + k0 + u * 8);
        __half* Bd = Bs + st * BSZH + brow * SH + bcs;
#pragma unroll
        for (int u = 0; u < NB16; u++) cp16(Bd + u * 8, Bp + k0 + u * 8);
        CP_COMMIT();
    };

    issue(0, 0);
    issue(1, 64);

    float c[2][NFRAG][4] = {};

    int st = 0;
    for (int i = 0; i < nsteps; i++) {
        if (i < nsteps - 1) asm volatile("cp.async.wait_group 1;");
        else                asm volatile("cp.async.wait_group 0;");
        __syncthreads();

        const unsigned* Ac = (const unsigned*)(As + st * ASZH);
        const unsigned* Bc = (const unsigned*)(Bs + st * BSZH);
#pragma unroll
        for (int ks = 0; ks < 4; ks++) {
            unsigned a[2][4];
#pragma unroll
            for (int ii = 0; ii < 2; ii++) {
                int r = m0 + ii * 16 + g;
                int idx = r * SH32 + ks * 8 + tig;
                a[ii][0] = Ac[idx];
                a[ii][1] = Ac[idx + 8 * SH32];
                a[ii][2] = Ac[idx + 4];
                a[ii][3] = Ac[idx + 8 * SH32 + 4];
            }
#pragma unroll
            for (int j = 0; j < NFRAG; j++) {
                int bidx = (n0 + j * 8 + g) * SH32 + ks * 8 + tig;
                unsigned b0 = Bc[bidx], b1 = Bc[bidx + 4];
#pragma unroll
                for (int ii = 0; ii < 2; ii++)
                    mma_fp16(c[ii][j], a[ii][0], a[ii][1], a[ii][2], a[ii][3], b0, b1);
            }
        }
        if (i + 2 < nsteps) issue((st + 2) % 3, (i + 2) * 64);
        st = (st + 1) % 3;
    }

#pragma unroll
    for (int i = 0; i < 2; i++) {
        int r0 = bm + m0 + i * 16 + g;
#pragma unroll
        for (int j = 0; j < NFRAG; j++) {
            int cc = bn + n0 + j * 8 + tig * 2;
            float v00 = c[i][j][0], v01 = c[i][j][1];
            float v10 = c[i][j][2], v11 = c[i][j][3];
            if (MODE == 1) {
                int hc = cc % DQK;
                if (hc >= DNOPE) {
                    int pi = (hc - DNOPE) >> 1;
                    float c0 = g_cos[r0 * 32 + pi], s0 = g_sin[r0 * 32 + pi];
                    float t0 = v00 * c0 - v01 * s0;
                    v01 = v00 * s0 + v01 * c0; v00 = t0;
                    float c1 = g_cos[(r0 + 8) * 32 + pi], s1 = g_sin[(r0 + 8) * 32 + pi];
                    float t1 = v10 * c1 - v11 * s1;
                    v11 = v10 * s1 + v11 * c1; v10 = t1;
                }
            }
            if (MODE == 1 || MODE == 2) {
                *(__half2*)&Ch[(size_t)r0 * N + cc] = __floats2half2_rn(v00, v01);
                *(__half2*)&Ch[(size_t)(r0 + 8) * N + cc] = __floats2half2_rn(v10, v11);
            } else {
                *(float2*)&Cf[(size_t)r0 * N + cc] = make_float2(v00, v01);
                *(float2*)&Cf[(size_t)(r0 + 8) * N + cc] = make_float2(v10, v11);
            }
        }
    }
}

// =================================================================
// LayerNorm(kv) -> fp16 kvn; RoPE(k_pe) -> fp16 kpe
// =================================================================
__global__ void ln_ropek_kernel(
    const float* __restrict__ kvf, const float* __restrict__ gamma,
    const float* __restrict__ beta,
    __half* __restrict__ kvnh, __half* __restrict__ kpeh)
{
    int row = blockIdx.x, tid = threadIdx.x;
    __shared__ float red[16];
    float a = kvf[row * KVF + tid];
    float b = kvf[row * KVF + 256 + tid];
    float s1 = a + b, s2 = a * a + b * b;
#pragma unroll
    for (int off = 16; off; off >>= 1) {
        s1 += __shfl_xor_sync(0xffffffffu, s1, off);
        s2 += __shfl_xor_sync(0xffffffffu, s2, off);
    }
    if ((tid & 31) == 0) { red[tid >> 5] = s1; red[8 + (tid >> 5)] = s2; }
    __syncthreads();
    float t1 = 0.f, t2 = 0.f;
#pragma unroll
    for (int i = 0; i < 8; i++) { t1 += red[i]; t2 += red[8 + i]; }
    float mean = t1 * (1.f / 512.f);
    float var  = t2 * (1.f / 512.f) - mean * mean;
    float rstd = rsqrtf(var + 1e-5f);
    kvnh[row * RANK + tid] =
        __float2half_rn((a - mean) * rstd * gamma[tid] + beta[tid]);
    kvnh[row * RANK + 256 + tid] =
        __float2half_rn((b - mean) * rstd * gamma[256 + tid] + beta[256 + tid]);
    if (tid < 32) {
        int i = tid;
        float c = g_cos[row * 32 + i], s = g_sin[row * 32 + i];
        float x1 = kvf[row * KVF + RANK + 2 * i];
        float x2 = kvf[row * KVF + RANK + 2 * i + 1];
        kpeh[row * DROPE + 2 * i]     = __float2half_rn(x1 * c - x2 * s);
        kpeh[row * DROPE + 2 * i + 1] = __float2half_rn(x1 * s + x2 * c);
    }
}

// =================================================================
// Flash attention v8: register softmax + double-buffered K/V (R15),
// V loaded ROW-MAJOR from kvbh (coalesced) and transposed in the LDS
// path via ldmatrix.x4.trans -> fp16 PV without the V^T global tensor.
// =================================================================
#define SQH  200    // Q/K smem stride in halves
#define SVH  136    // V row stride in halves (row kv, 128 dv + pad 8)
#define QR   128
#define KSZH (64 * SQH)
#define VSZH (64 * SVH)
#define ATTN_SMEM_BYTES ((QR*SQH + 2*KSZH + 2*VSZH) * 2)

__global__ void __launch_bounds__(256, 1) attn_kernel(
    const __half* __restrict__ qh, const __half* __restrict__ kvbh,
    const __half* __restrict__ kpeh, __half* __restrict__ ah)
{
    extern __shared__ char smb[];
    __half* Qh = (__half*)smb;                  // [128][200]
    __half* Kh = Qh + QR * SQH;                 // [2][64][200]
    __half* Vh = Kh + 2 * KSZH;                 // [2][64][136]  V row-major

    const int tid = threadIdx.x;
    const int lane = tid & 31, w = tid >> 5;
    const int g = lane >> 2, tig = lane & 3;
    const int m0 = w * 16;                       // warp q-row base
    const int h  = blockIdx.y;
    const int iq = (int)(gridDim.x - 1) - (int)blockIdx.x;  // big tiles first
    const int q0 = iq * QR;
    const int lr = tid >> 2;                     // 0..63  (K/V loads)
    const int seg = tid & 3;                     // 0..3
    const int qr = tid >> 1;                     // 0..127 (Q loads)
    const int qs = tid & 1;                      // 0..1

    auto issue_kv = [&](int jt, int buf) {
        int t = jt * 64 + lr;
        const __half* kn = kvbh + (size_t)t * KVBSTRIDE + h * 256;
        const __half* kp = kpeh + (size_t)t * DROPE;
        __half* Kb = Kh + buf * KSZH;
#pragma unroll
        for (int u = 0; u < 6; u++) {
            int k = seg * 48 + u * 8;
            const __half* src = (k < 128) ? (kn + k) : (kp + (k - 128));
            cp16(&Kb[lr * SQH + k], src);
        }
        // V rows: 128 halves per kv row, 4 threads/row x 4 cp16
        const __half* vp = kn + 128;
        __half* Vb = Vh + buf * VSZH;
#pragma unroll
        for (int u = 0; u < 4; u++) {
            int cidx = (seg * 4 + u) * 8;
            cp16(&Vb[lr * SVH + cidx], vp + cidx);
        }
        CP_COMMIT();
    };

    issue_kv(0, 0);
    {
        const __half* src = qh + (size_t)(q0 + qr) * QSTRIDE + h * DQK + qs * 96;
#pragma unroll
        for (int u = 0; u < 12; u++)
            *(uint4*)&Qh[qr * SQH + qs * 96 + u * 8] = *(const uint4*)(src + u * 8);
    }

    // ldmatrix.trans per-lane offset within V tile:
    //   tile = lane>>3 (0..3), r = lane&7
    //   row  = (lane>>4)*8 + r      (tiles 2,3 -> +8 kv rows)
    //   col  = ((lane>>3)&1)*8      (tiles 1,3 -> +8 dv cols)
    const unsigned sV = (unsigned)__cvta_generic_to_shared(Vh);
    const unsigned vlane = ((((lane >> 4) * 8 + (lane & 7)) * SVH
                             + ((lane >> 3) & 1) * 8) * 2);

    float mr0 = -INFINITY, mr1 = -INFINITY;
    float lr0 = 0.f, lr1 = 0.f;
    float o[16][4] = {};

    const int jmax = 2 * iq + 1;
    for (int jt = 0; jt <= jmax; jt++) {
        __syncthreads();
        if (jt < jmax) {
            issue_kv(jt + 1, (jt + 1) & 1);
            asm volatile("cp.async.wait_group 1;");
        } else {
            asm volatile("cp.async.wait_group 0;");
        }
        __syncthreads();

        const unsigned* K32 = (const unsigned*)(Kh + (jt & 1) * KSZH);
        const unsigned* Q32 = (const unsigned*)Qh;
        const unsigned vbase = sV + (jt & 1) * (VSZH * 2) + vlane;

        // ---- S = Q K^T, fp16 (12 k16-steps) ----
        float s[8][4] = {};
#pragma unroll
        for (int k0 = 0; k0 < 96; k0 += 8) {
            int ai = (m0 + g) * (SQH / 2) + k0 + tig;
            unsigned a0 = Q32[ai];
            unsigned a2 = Q32[ai + 4];
            unsigned a1 = Q32[ai + 8 * (SQH / 2)];
            unsigned a3 = Q32[ai + 8 * (SQH / 2) + 4];
#pragma unroll
            for (int j = 0; j < 8; j++) {
                int bi = (j * 8 + g) * (SQH / 2) + k0 + tig;
                mma_fp16(s[j], a0, a1, a2, a3, K32[bi], K32[bi + 4]);
            }
        }

        // ---- mask + scale in registers ----
        {
            int gr0 = q0 + m0 + g, gr1 = gr0 + 8;
#pragma unroll
            for (int j = 0; j < 8; j++) {
                int gc0 = jt * 64 + j * 8 + tig * 2, gc1 = gc0 + 1;
                s[j][0] = (gr0 >= gc0) ? s[j][0] * SCALE : -INFINITY;
                s[j][1] = (gr0 >= gc1) ? s[j][1] * SCALE : -INFINITY;
                s[j][2] = (gr1 >= gc0) ? s[j][2] * SCALE : -INFINITY;
                s[j][3] = (gr1 >= gc1) ? s[j][3] * SCALE : -INFINITY;
            }
        }

        // ---- register softmax: quad shfl reductions ----
        float mx0 = -INFINITY, mx1 = -INFINITY;
#pragma unroll
        for (int j = 0; j < 8; j++) {
            mx0 = fmaxf(mx0, fmaxf(s[j][0], s[j][1]));
            mx1 = fmaxf(mx1, fmaxf(s[j][2], s[j][3]));
        }
        mx0 = fmaxf(mx0, __shfl_xor_sync(0xffffffffu, mx0, 1));
        mx0 = fmaxf(mx0, __shfl_xor_sync(0xffffffffu, mx0, 2));
        mx1 = fmaxf(mx1, __shfl_xor_sync(0xffffffffu, mx1, 1));
        mx1 = fmaxf(mx1, __shfl_xor_sync(0xffffffffu, mx1, 2));
        float mn0 = fmaxf(mr0, mx0), mn1 = fmaxf(mr1, mx1);
        float al0 = __expf(mr0 - mn0), al1 = __expf(mr1 - mn1);
        float sum0 = 0.f, sum1 = 0.f;
#pragma unroll
        for (int j = 0; j < 8; j++) {
            s[j][0] = __expf(s[j][0] - mn0);
            s[j][1] = __expf(s[j][1] - mn0);
            s[j][2] = __expf(s[j][2] - mn1);
            s[j][3] = __expf(s[j][3] - mn1);
            sum0 += s[j][0] + s[j][1];
            sum1 += s[j][2] + s[j][3];
        }
        sum0 += __shfl_xor_sync(0xffffffffu, sum0, 1);
        sum0 += __shfl_xor_sync(0xffffffffu, sum0, 2);
        sum1 += __shfl_xor_sync(0xffffffffu, sum1, 1);
        sum1 += __shfl_xor_sync(0xffffffffu, sum1, 2);
        lr0 = lr0 * al0 + sum0;  mr0 = mn0;
        lr1 = lr1 * al1 + sum1;  mr1 = mn1;

        // ---- rescale O, then O += P @ V  (V frags via ldmatrix.trans) ----
#pragma unroll
        for (int nt = 0; nt < 16; nt++) {
            o[nt][0] *= al0; o[nt][1] *= al0;
            o[nt][2] *= al1; o[nt][3] *= al1;
        }
#pragma unroll
        for (int ks = 0; ks < 4; ks++) {
            unsigned a0 = pack2(s[2 * ks][0],     s[2 * ks][1]);
            unsigned a1 = pack2(s[2 * ks][2],     s[2 * ks][3]);
            unsigned a2 = pack2(s[2 * ks + 1][0], s[2 * ks + 1][1]);
            unsigned a3 = pack2(s[2 * ks + 1][2], s[2 * ks + 1][3]);
            unsigned b[16][2];
#pragma unroll
            for (int nf = 0; nf < 8; nf++) {
                unsigned t0, t1, t2, t3;
                LDSM4T(t0, t1, t2, t3,
                       vbase + (ks * 16 * SVH + nf * 16) * 2);
                b[2 * nf][0] = t0;     b[2 * nf][1] = t2;
                b[2 * nf + 1][0] = t1; b[2 * nf + 1][1] = t3;
            }
#pragma unroll
            for (int nt = 0; nt < 16; nt++)
                mma_fp16(o[nt], a0, a1, a2, a3, b[nt][0], b[nt][1]);
        }
    }

    {
        float inv0 = 1.f / lr0;
        float inv1 = 1.f / lr1;
        size_t r0 = (size_t)(q0 + m0 + g) * OSTRIDE + h * DV;
        size_t r1 = (size_t)(q0 + m0 + 8 + g) * OSTRIDE + h * DV;
#pragma unroll
        for (int nt = 0; nt < 16; nt++) {
            int cc = nt * 8 + tig * 2;
            *(__half2*)(ah + r0 + cc) = __floats2half2_rn(o[nt][0] * inv0, o[nt][1] * inv0);
            *(__half2*)(ah + r1 + cc) = __floats2half2_rn(o[nt][2] * inv1, o[nt][3] * inv1);
        }
    }
}

// =================================================================
// launch
// =================================================================
#define GSMH8 (3 * (128 * SH + 128 * SH) * 2)   // 110592 B
#define GSMH4 (3 * (128 * SH + 64 * SH) * 2)    // 82944 B

extern "C" void kernel_launch(void* const* d_in, const int* in_sizes, int n_in,
                              void* d_out, int out_size)
{
    const float* x     = (const float*)d_in[0];
    const float* wq    = (const float*)d_in[1];
    const float* wkv_a = (const float*)d_in[2];
    const float* gamma = (const float*)d_in[3];
    const float* beta  = (const float*)d_in[4];
    const float* wkv_b = (const float*)d_in[5];
    const float* wo    = (const float*)d_in[6];
    float* out = (float*)d_out;

    float *gkvf;
    __half *qh, *kvbh, *kpeh, *xh, *wqh, *wkvah, *wkvbh, *woh, *kvnh, *ah;
    cudaGetSymbolAddress((void**)&gkvf,  g_kvfull);
    cudaGetSymbolAddress((void**)&qh,    g_qh);
    cudaGetSymbolAddress((void**)&kvbh,  g_kvbh);
    cudaGetSymbolAddress((void**)&kpeh,  g_kpeh);
    cudaGetSymbolAddress((void**)&xh,    g_xh);
    cudaGetSymbolAddress((void**)&wqh,   g_wqh);
    cudaGetSymbolAddress((void**)&wkvah, g_wkvah);
    cudaGetSymbolAddress((void**)&wkvbh, g_wkvbh);
    cudaGetSymbolAddress((void**)&woh,   g_woh);
    cudaGetSymbolAddress((void**)&kvnh,  g_kvnh);
    cudaGetSymbolAddress((void**)&ah,    g_ah);

    cudaFuncSetAttribute(gemm_h<8, 1>, cudaFuncAttributeMaxDynamicSharedMemorySize, GSMH8);
    cudaFuncSetAttribute(gemm_h<8, 2>, cudaFuncAttributeMaxDynamicSharedMemorySize, GSMH8);
    cudaFuncSetAttribute(gemm_h<8, 0>, cudaFuncAttributeMaxDynamicSharedMemorySize, GSMH8);
    cudaFuncSetAttribute(gemm_h<4, 0>, cudaFuncAttributeMaxDynamicSharedMemorySize, GSMH4);
    cudaFuncSetAttribute(attn_kernel, cudaFuncAttributeMaxDynamicSharedMemorySize, ATTN_SMEM_BYTES);

    // launch order fixed so ncu -s 5 captures the kvb GEMM:
    // 0: rope_table, 1: tohalf_all, 2: q GEMM, 3: kva GEMM, 4: ln, 5: kvb GEMM
    rope_table_kernel<<<(TT * 32) / 256, 256>>>();
    tohalf_all_kernel<<<(N4_TOT + 255) / 256, 256>>>(x, wq, wkv_a, wkv_b, wo);

    // q = x @ wq^T (+fused rope) -> fp16       4096 x 3072, K=2048
    gemm_h<8, 1><<<dim3(3072 / 128, TT / 128), 256, GSMH8>>>(
        xh, wqh, nullptr, qh, 3072, DMODEL);
    // kv_full = x @ wkv_a^T -> fp32            4096 x 576, K=2048
    gemm_h<4, 0><<<dim3(KVF / 64, TT / 128), 256, GSMH4>>>(
        xh, wkvah, gkvf, nullptr, KVF, DMODEL);
    // layernorm(kv) -> fp16 kvn; rope(k_pe) -> fp16
    ln_ropek_kernel<<<TT, 256>>>(gkvf, gamma, beta, kvnh, kpeh);
    // kvb = kvn @ wkv_b^T -> fp16              4096 x 4096, K=512
    gemm_h<8, 2><<<dim3(KVBSTRIDE / 128, TT / 128), 256, GSMH8>>>(
        kvnh, wkvbh, nullptr, kvbh, KVBSTRIDE, RANK);
    // attention -> fp16 (V transposed in-kernel via ldmatrix.trans)
    attn_kernel<<<dim3(TT / QR, NH), 256, ATTN_SMEM_BYTES>>>(qh, kvbh, kpeh, ah);
    // out = attn @ wo^T -> fp32                4096 x 2048, K=2048
    gemm_h<8, 0><<<dim3(DMODEL / 128, TT / 128), 256, GSMH8>>>(
        ah, woh, out, nullptr, DMODEL, DMODEL);
}